// round 12
// baseline (speedup 1.0000x reference)
#include <cuda_runtime.h>
#include <cuda_bf16.h>
#include <cuda_fp16.h>
#include <cstdint>

#define HH 128
#define WWID 128
#define NBATCH 8
#define CIN 64
#define HW (HH*WWID)

// ---------------- device scratch ----------------
__device__ __half g_q0[NBATCH * HW * CIN];     // channel-last fp16 plane
__device__ __half g_q1[NBATCH * HW * CIN];
__device__ float g_bcoef[NBATCH * 54 * HW];
__device__ uint32_t g_wF[7 * 9 * 2048];        // [l][tap][kc][nh][lane][8] fragment regs
__device__ float g_shiftT[7 * 64];

// smem layout (bytes): A 3 slots (dy) of 128px*144B = 18432B -> 55296
// shift @55296 (256B), bases @55552 (216B).
// acc (128*66*4 = 33792) and hs (@34816, 128*40*4 = 20480) reuse the A region.
#define A_SLOT 18432u
#define SH_OFF 55296u
#define BAS_OFF 55552u
#define HS_OFF 34816u
#define SMEM_BYTES 55808

__device__ __forceinline__ float tanh_fast(float x) {
    float a = fminf(fmaxf(x, -9.f), 9.f);
    float e = __expf(2.f * a);
    return __fdividef(e - 1.f, e + 1.f);
}
__device__ __forceinline__ void cp16(uint32_t dst, const void* src) {
    asm volatile("cp.async.cg.shared.global [%0], [%1], 16;" :: "r"(dst), "l"(src));
}
__device__ __forceinline__ uint32_t s2u(const void* p) {
    return (uint32_t)__cvta_generic_to_shared(p);
}
__device__ __forceinline__ void ldsm4(uint32_t* a, uint32_t addr) {
    asm volatile("ldmatrix.sync.aligned.m8n8.x4.shared.b16 {%0,%1,%2,%3}, [%4];"
                 : "=r"(a[0]), "=r"(a[1]), "=r"(a[2]), "=r"(a[3]) : "r"(addr));
}
__device__ __forceinline__ void mma16816(float* c, const uint32_t* a, const uint32_t* b) {
    asm volatile("mma.sync.aligned.m16n8k16.row.col.f32.f16.f16.f32 "
                 "{%0,%1,%2,%3}, {%4,%5,%6,%7}, {%8,%9}, {%0,%1,%2,%3};"
                 : "+f"(c[0]), "+f"(c[1]), "+f"(c[2]), "+f"(c[3])
                 : "r"(a[0]), "r"(a[1]), "r"(a[2]), "r"(a[3]), "r"(b[0]), "r"(b[1]));
}

// ---------------------------------------------------------------------------
// Prep: BN-fold weights -> fp16 per-lane MMA fragments.
// reg r = nt*2 + j:  n = nh*32 + nt*8 + lane/4,  k = kc*16 + (lane%4)*2 + j*8
// Layers 0..5: 64 oc. Layer 6 (last): 36 oc zero-padded to 64.
// ---------------------------------------------------------------------------
__global__ void prep_weights(
    const float* __restrict__ w0, const float* __restrict__ b0,
    const float* __restrict__ g0, const float* __restrict__ be0,
    const float* __restrict__ m0, const float* __restrict__ v0,
    const float* __restrict__ wm, const float* __restrict__ bm,
    const float* __restrict__ gm, const float* __restrict__ bem,
    const float* __restrict__ mm, const float* __restrict__ vm,
    const float* __restrict__ wl, const float* __restrict__ bl,
    const float* __restrict__ gl, const float* __restrict__ bel,
    const float* __restrict__ ml, const float* __restrict__ vl,
    uint32_t* __restrict__ wF, float* __restrict__ shiftT)
{
    const int tap = blockIdx.x, l = blockIdx.y;
    const float *w, *bb, *g, *be, *m, *v;
    int OC = 64;
    if (l == 0)      { w = w0; bb = b0; g = g0; be = be0; m = m0; v = v0; }
    else if (l <= 5) {
        int i = l - 1;
        w = wm + (size_t)i * 64 * 64 * 9; bb = bm + i * 64; g = gm + i * 64;
        be = bem + i * 64; m = mm + i * 64; v = vm + i * 64;
    } else { w = wl; bb = bl; g = gl; be = bel; m = ml; v = vl; OC = 36; }

    uint32_t* out = wF + (size_t)(l * 9 + tap) * 2048;
    for (int e = threadIdx.x; e < 2048; e += blockDim.x) {
        int kc = e >> 9, nh = (e >> 8) & 1, lane = (e >> 3) & 31, r = e & 7;
        int nt = r >> 1, j = r & 1;
        int n = nh * 32 + nt * 8 + (lane >> 2);
        int k = kc * 16 + (lane & 3) * 2 + j * 8;
        float f0 = 0.f, f1 = 0.f;
        if (n < OC) {
            float sc = g[n] * rsqrtf(v[n] + 1e-5f);
            f0 = w[((size_t)n * 64 + k) * 9 + tap] * sc;
            f1 = w[((size_t)n * 64 + k + 1) * 9 + tap] * sc;
        }
        unsigned u0 = __half_as_ushort(__float2half_rn(f0));
        unsigned u1 = __half_as_ushort(__float2half_rn(f1));
        out[e] = u0 | (u1 << 16);
    }
    if (tap == 0)
        for (int oc = threadIdx.x; oc < 64; oc += blockDim.x) {
            float s = 0.f;
            if (oc < OC) {
                float sc = g[oc] * rsqrtf(v[oc] + 1e-5f);
                s = (bb[oc] - m[oc]) * sc + be[oc];
            }
            shiftT[l * 64 + oc] = s;
        }
}

// ---------------------------------------------------------------------------
// x [b][c][h][w] fp32 -> channel-last fp16 [b][h][w][c]
// ---------------------------------------------------------------------------
__global__ __launch_bounds__(128) void conv_input(
    const float* __restrict__ x, __half* __restrict__ XQ)
{
    const int w = threadIdx.x, r = blockIdx.x, b = blockIdx.y;
    unsigned hp[32];
    #pragma unroll
    for (int j = 0; j < 32; j++) {
        float f0 = x[((size_t)(b * 64 + 2 * j) * 128 + r) * 128 + w];
        float f1 = x[((size_t)(b * 64 + 2 * j + 1) * 128 + r) * 128 + w];
        hp[j] = (unsigned)__half_as_ushort(__float2half_rn(f0)) |
                ((unsigned)__half_as_ushort(__float2half_rn(f1)) << 16);
    }
    uint4* dh = (uint4*)(XQ + ((size_t)(b * 128 + r) * 128 + w) * 64);
    #pragma unroll
    for (int q = 0; q < 8; q++)
        dh[q] = make_uint4(hp[4*q], hp[4*q+1], hp[4*q+2], hp[4*q+3]);
}

// ---------------------------------------------------------------------------
// Warp-MMA conv layer, fp16, dx-in-epilogue (3 accumulator planes).
// CTA = (row, batch). 8 warps = 4 M-stripes(32px) x 2 N-halves(32oc).
// Mainloop: dy(3) x kc(4): 2 LDSM + dx(3) x (2 LDG.128 B + 8 MMA).
// Epilogue: out(w) = D0(w-1) + D1(w) + D2(w+1) via 3-pass smem reduction.
// LAST=0: BN+tanh -> fp16 plane.  LAST=1 (64->36): + bcoef einsum.
// ---------------------------------------------------------------------------
template<int LAST>
__global__ __launch_bounds__(256, 2) void conv_mma_t(
    const __half* __restrict__ XQ, __half* __restrict__ YQ,
    const uint32_t* __restrict__ wFl, const float* __restrict__ shiftl,
    const float* __restrict__ bases, float* __restrict__ bco)
{
    extern __shared__ __align__(16) char sm[];
    const uint32_t alu = s2u(sm);
    const int tid = threadIdx.x, lane = tid & 31, wid = tid >> 5;
    const int ms = wid >> 1, nh = wid & 1;
    const int r = blockIdx.x, b = blockIdx.y;

    const uint32_t aoff = (uint32_t)(lane & 15) * 144u + (uint32_t)((lane >> 4) & 1) * 16u;

    if (tid < 64) ((float*)(sm + SH_OFF))[tid] = shiftl[tid];
    if (LAST && tid < 54) ((float*)(sm + BAS_OFF))[tid] = bases[tid];

    // zero off-image row slots (dy row buffer fully zero at image border)
    if (r == 0 || r == 127) {
        uint4 z = make_uint4(0, 0, 0, 0);
        char* base = sm + (r ? 2 : 0) * A_SLOT;
        for (int i = tid; i < 1152; i += 256)
            *(uint4*)(base + i * 16) = z;
    }

    // ---- async copies: 3 A rows (no pixel halo needed) ----
    #pragma unroll
    for (int dy = 0; dy < 3; dy++) {
        int rimg = r + dy - 1;
        if ((unsigned)rimg >= (unsigned)HH) continue;
        const char* src = (const char*)XQ + (size_t)(b * 128 + rimg) * 16384;
        uint32_t dstb = alu + (uint32_t)dy * A_SLOT;
        for (int i = tid; i < 1024; i += 256) {
            int px = i >> 3, c = i & 7;
            cp16(dstb + (uint32_t)px * 144u + (uint32_t)c * 16u,
                 src + px * 128 + c * 16);
        }
    }
    asm volatile("cp.async.commit_group;" ::: "memory");
    asm volatile("cp.async.wait_group 0;" ::: "memory");
    __syncthreads();

    float cacc[3][2][4][4];
    #pragma unroll
    for (int dx = 0; dx < 3; dx++)
        #pragma unroll
        for (int mt = 0; mt < 2; mt++)
            #pragma unroll
            for (int nt = 0; nt < 4; nt++)
                #pragma unroll
                for (int j = 0; j < 4; j++) cacc[dx][mt][nt][j] = 0.f;

    // ---- mainloop: dy x kc, A loaded ONCE, 3 dx MMA into separate planes ----
    #pragma unroll
    for (int dy = 0; dy < 3; dy++) {
        const uint32_t aB = alu + (uint32_t)dy * A_SLOT;
        #pragma unroll
        for (int kc = 0; kc < 4; kc++) {
            const uint32_t kb = (uint32_t)kc * 32u;
            uint32_t ah[2][4];
            ldsm4(ah[0], aB + (uint32_t)(ms * 32) * 144u + kb + aoff);
            ldsm4(ah[1], aB + (uint32_t)(ms * 32 + 16) * 144u + kb + aoff);

            #pragma unroll
            for (int dx = 0; dx < 3; dx++) {
                const int tap = dy * 3 + dx;
                const uint4* f = (const uint4*)(wFl +
                    ((((size_t)tap * 4 + kc) * 2 + nh) * 32 + lane) * 8);
                uint4 q0 = f[0], q1 = f[1];
                uint32_t bh[4][2];
                bh[0][0] = q0.x; bh[0][1] = q0.y; bh[1][0] = q0.z; bh[1][1] = q0.w;
                bh[2][0] = q1.x; bh[2][1] = q1.y; bh[3][0] = q1.z; bh[3][1] = q1.w;

                #pragma unroll
                for (int mt = 0; mt < 2; mt++)
                    #pragma unroll
                    for (int nt = 0; nt < 4; nt++)
                        mma16816(cacc[dx][mt][nt], ah[mt], bh[nt]);
            }
        }
    }
    __syncthreads();   // A region now reusable as acc

    // ---- 3-pass shifted reduction: out(w) = D0(w-1) + D1(w) + D2(w+1) ----
    float* acc = (float*)sm;
    const int rb = ms * 32 + (lane >> 2);
    const int cb = nh * 32 + (lane & 3) * 2;

    // pass 1: D1 (no shift) - plain stores, all rows covered exactly once
    #pragma unroll
    for (int mt = 0; mt < 2; mt++)
        #pragma unroll
        for (int nt = 0; nt < 4; nt++) {
            int row = rb + mt * 16, col = cb + nt * 8;
            *(float2*)&acc[row * 66 + col] =
                make_float2(cacc[1][mt][nt][0], cacc[1][mt][nt][1]);
            *(float2*)&acc[(row + 8) * 66 + col] =
                make_float2(cacc[1][mt][nt][2], cacc[1][mt][nt][3]);
        }
    __syncthreads();

    // pass 2: D0 -> row+1 (skip source row 127); unique targets across warps
    #pragma unroll
    for (int mt = 0; mt < 2; mt++)
        #pragma unroll
        for (int nt = 0; nt < 4; nt++) {
            int row = rb + mt * 16, col = cb + nt * 8;
            if (row < 127) {
                float2* p = (float2*)&acc[(row + 1) * 66 + col];
                float2 vv = *p;
                vv.x += cacc[0][mt][nt][0]; vv.y += cacc[0][mt][nt][1];
                *p = vv;
            }
            {
                float2* p = (float2*)&acc[(row + 9) * 66 + col];
                float2 vv = *p;
                vv.x += cacc[0][mt][nt][2]; vv.y += cacc[0][mt][nt][3];
                *p = vv;
            }
        }
    __syncthreads();

    // pass 3: D2 -> row-1 (skip source row 0)
    #pragma unroll
    for (int mt = 0; mt < 2; mt++)
        #pragma unroll
        for (int nt = 0; nt < 4; nt++) {
            int row = rb + mt * 16, col = cb + nt * 8;
            if (row > 0) {
                float2* p = (float2*)&acc[(row - 1) * 66 + col];
                float2 vv = *p;
                vv.x += cacc[2][mt][nt][0]; vv.y += cacc[2][mt][nt][1];
                *p = vv;
            }
            {
                float2* p = (float2*)&acc[(row + 7) * 66 + col];
                float2 vv = *p;
                vv.x += cacc[2][mt][nt][2]; vv.y += cacc[2][mt][nt][3];
                *p = vv;
            }
        }
    __syncthreads();

    if (!LAST) {
        // ---- epilogue: tanh -> fp16 plane ----
        const int px = tid >> 1, ocb = (tid & 1) * 32;
        const float* shp = (const float*)(sm + SH_OFF) + ocb;
        const float* ap = acc + px * 66 + ocb;
        unsigned hp[16];
        #pragma unroll
        for (int j = 0; j < 16; j++) {
            float t0 = tanh_fast(ap[2 * j] + shp[2 * j]);
            float t1 = tanh_fast(ap[2 * j + 1] + shp[2 * j + 1]);
            hp[j] = (unsigned)__half_as_ushort(__float2half_rn(t0)) |
                    ((unsigned)__half_as_ushort(__float2half_rn(t1)) << 16);
        }
        uint4* dh = (uint4*)(YQ + ((size_t)(b * 128 + r) * 128 + px) * 64 + ocb);
        #pragma unroll
        for (int q = 0; q < 4; q++)
            dh[q] = make_uint4(hp[4*q], hp[4*q+1], hp[4*q+2], hp[4*q+3]);
    } else {
        // ---- epilogue: tanh (36 oc) -> hs, then bcoef einsum ----
        float* hsP = (float*)(sm + HS_OFF);
        const float* shp = (const float*)(sm + SH_OFF);
        {
            const int px = tid >> 1, half = tid & 1;
            #pragma unroll
            for (int j = 0; j < 18; j++) {
                int oc = half * 18 + j;
                hsP[px * 40 + oc] = tanh_fast(acc[px * 66 + oc] + shp[oc]);
            }
        }
        __syncthreads();
        {
            const int px = tid >> 1, half = tid & 1;
            const float* basS = (const float*)(sm + BAS_OFF);
            const float* hp = hsP + px * 40;
            #pragma unroll
            for (int mm = 0; mm < 3; mm++) {
                int m = half * 3 + mm;
                float hm[6];
                #pragma unroll
                for (int k = 0; k < 6; k++) hm[k] = hp[m * 6 + k];
                #pragma unroll
                for (int l = 0; l < 9; l++) {
                    float s = 0.f;
                    #pragma unroll
                    for (int k = 0; k < 6; k++) s = fmaf(hm[k], basS[k * 9 + l], s);
                    bco[((size_t)(b * 6 + m) * 9 + l) * HW + r * 128 + px] = s;
                }
            }
        }
    }
}

// ---------------------------------------------------------------------------
__global__ __launch_bounds__(256) void dynconv(
    const float* __restrict__ x, const float* __restrict__ bco,
    float* __restrict__ out)
{
    const int b = blockIdx.y;
    const int pix = blockIdx.x * 256 + threadIdx.x;
    const int h = pix >> 7, w = pix & 127;

    float bc[54];
    const float* bcb = bco + (size_t)b * 54 * HW + pix;
    #pragma unroll
    for (int i = 0; i < 54; i++) bc[i] = bcb[(size_t)i * HW];

    bool ok[9]; int off[9];
    #pragma unroll
    for (int dy = 0; dy < 3; dy++)
        #pragma unroll
        for (int dx = 0; dx < 3; dx++) {
            int k = dy * 3 + dx;
            int hh = h + dy - 1, ww = w + dx - 1;
            ok[k] = ((unsigned)hh < HH) && ((unsigned)ww < WWID);
            off[k] = hh * WWID + ww;
        }

    const float* xb = x + (size_t)b * CIN * HW;
    float* ob = out + (size_t)b * (CIN * 6) * HW + pix;

    for (int c = 0; c < CIN; c++) {
        const float* xc = xb + c * HW;
        float v[9];
        #pragma unroll
        for (int k = 0; k < 9; k++) v[k] = ok[k] ? __ldg(xc + off[k]) : 0.f;
        #pragma unroll
        for (int m = 0; m < 6; m++) {
            float s = 0.f;
            #pragma unroll
            for (int k = 0; k < 9; k++) s = fmaf(bc[m * 9 + k], v[k], s);
            ob[(size_t)(c * 6 + m) * HW] = s;
        }
    }
}

// ---------------------------------------------------------------------------
extern "C" void kernel_launch(void* const* d_in, const int* in_sizes, int n_in,
                              void* d_out, int out_size) {
    const float* x    = (const float*)d_in[0];
    const float* w0   = (const float*)d_in[1];
    const float* b0   = (const float*)d_in[2];
    const float* g0   = (const float*)d_in[3];
    const float* be0  = (const float*)d_in[4];
    const float* m0   = (const float*)d_in[5];
    const float* v0   = (const float*)d_in[6];
    const float* wm   = (const float*)d_in[7];
    const float* bm   = (const float*)d_in[8];
    const float* gm   = (const float*)d_in[9];
    const float* bem  = (const float*)d_in[10];
    const float* mm   = (const float*)d_in[11];
    const float* vm   = (const float*)d_in[12];
    const float* wl   = (const float*)d_in[13];
    const float* bl   = (const float*)d_in[14];
    const float* gl   = (const float*)d_in[15];
    const float* bel  = (const float*)d_in[16];
    const float* ml   = (const float*)d_in[17];
    const float* vl   = (const float*)d_in[18];
    const float* bases= (const float*)d_in[19];

    __half *q0, *q1;
    float *bco, *shiftT;
    uint32_t* wF;
    cudaGetSymbolAddress((void**)&q0, g_q0);
    cudaGetSymbolAddress((void**)&q1, g_q1);
    cudaGetSymbolAddress((void**)&bco,  g_bcoef);
    cudaGetSymbolAddress((void**)&wF,   g_wF);
    cudaGetSymbolAddress((void**)&shiftT, g_shiftT);

    cudaFuncSetAttribute(conv_mma_t<0>, cudaFuncAttributeMaxDynamicSharedMemorySize, SMEM_BYTES);
    cudaFuncSetAttribute(conv_mma_t<1>, cudaFuncAttributeMaxDynamicSharedMemorySize, SMEM_BYTES);

    dim3 pgrd(9, 7);
    prep_weights<<<pgrd, 256>>>(w0, b0, g0, be0, m0, v0,
                                wm, bm, gm, bem, mm, vm,
                                wl, bl, gl, bel, ml, vl, wF, shiftT);

    dim3 sgrd(128, NBATCH);
    conv_input<<<sgrd, 128>>>(x, q0);

    __half* buf[2] = { q0, q1 };
    for (int l = 0; l < 6; l++) {
        conv_mma_t<0><<<sgrd, 256, SMEM_BYTES>>>(
            buf[l & 1], buf[(l + 1) & 1],
            wF + (size_t)l * 9 * 2048, shiftT + l * 64, nullptr, nullptr);
    }
    // last layer (64->36) + bcoef, reads layer-5 output plane (q0)
    conv_mma_t<1><<<sgrd, 256, SMEM_BYTES>>>(
        q0, nullptr,
        wF + (size_t)6 * 9 * 2048, shiftT + 6 * 64, bases, bco);

    dim3 grd2(HW / 256, NBATCH);
    dynconv<<<grd2, 256>>>(x, bco, (float*)d_out);
}

// round 13
// speedup vs baseline: 1.1963x; 1.1963x over previous
#include <cuda_runtime.h>
#include <cuda_bf16.h>
#include <cuda_fp16.h>
#include <cstdint>

#define HH 128
#define WWID 128
#define NBATCH 8
#define CIN 64
#define HW (HH*WWID)

// ---------------- device scratch ----------------
__device__ __half g_q0[NBATCH * HW * CIN];     // channel-last fp16 plane
__device__ __half g_q1[NBATCH * HW * CIN];
__device__ float g_bcoef[NBATCH * 54 * HW];
__device__ uint32_t g_wF[7 * 9 * 2048];        // [l][tap][kc][nh][lane][8] fragment regs
__device__ float g_shiftT[7 * 64];

// smem (bytes): A halo 4 slots (rows 2r-1..2r+2) of 130px*144B = 18720 -> 74880
// shift @74880 (256B), bases @75136 (216B).
// acc (256*66*4 = 67584) reuses the A region after the mainloop.
#define A_SLOT 18720u
#define SH_OFF 74880u
#define BAS_OFF 75136u
#define SMEM_BYTES 75392

__device__ __forceinline__ float tanh_fast(float x) {
    float a = fminf(fmaxf(x, -9.f), 9.f);
    float e = __expf(2.f * a);
    return __fdividef(e - 1.f, e + 1.f);
}
__device__ __forceinline__ void cp16(uint32_t dst, const void* src) {
    asm volatile("cp.async.cg.shared.global [%0], [%1], 16;" :: "r"(dst), "l"(src));
}
__device__ __forceinline__ uint32_t s2u(const void* p) {
    return (uint32_t)__cvta_generic_to_shared(p);
}
__device__ __forceinline__ void ldsm4(uint32_t* a, uint32_t addr) {
    asm volatile("ldmatrix.sync.aligned.m8n8.x4.shared.b16 {%0,%1,%2,%3}, [%4];"
                 : "=r"(a[0]), "=r"(a[1]), "=r"(a[2]), "=r"(a[3]) : "r"(addr));
}
__device__ __forceinline__ void mma16816(float* c, const uint32_t* a, const uint32_t* b) {
    asm volatile("mma.sync.aligned.m16n8k16.row.col.f32.f16.f16.f32 "
                 "{%0,%1,%2,%3}, {%4,%5,%6,%7}, {%8,%9}, {%0,%1,%2,%3};"
                 : "+f"(c[0]), "+f"(c[1]), "+f"(c[2]), "+f"(c[3])
                 : "r"(a[0]), "r"(a[1]), "r"(a[2]), "r"(a[3]), "r"(b[0]), "r"(b[1]));
}

// ---------------------------------------------------------------------------
// Prep: BN-fold weights -> fp16 per-lane MMA fragments.
// reg r = nt*2 + j:  n = nh*32 + nt*8 + lane/4,  k = kc*16 + (lane%4)*2 + j*8
// Layers 0..5: 64 oc. Layer 6 (last): 36 oc zero-padded to 64.
// ---------------------------------------------------------------------------
__global__ void prep_weights(
    const float* __restrict__ w0, const float* __restrict__ b0,
    const float* __restrict__ g0, const float* __restrict__ be0,
    const float* __restrict__ m0, const float* __restrict__ v0,
    const float* __restrict__ wm, const float* __restrict__ bm,
    const float* __restrict__ gm, const float* __restrict__ bem,
    const float* __restrict__ mm, const float* __restrict__ vm,
    const float* __restrict__ wl, const float* __restrict__ bl,
    const float* __restrict__ gl, const float* __restrict__ bel,
    const float* __restrict__ ml, const float* __restrict__ vl,
    uint32_t* __restrict__ wF, float* __restrict__ shiftT)
{
    const int tap = blockIdx.x, l = blockIdx.y;
    const float *w, *bb, *g, *be, *m, *v;
    int OC = 64;
    if (l == 0)      { w = w0; bb = b0; g = g0; be = be0; m = m0; v = v0; }
    else if (l <= 5) {
        int i = l - 1;
        w = wm + (size_t)i * 64 * 64 * 9; bb = bm + i * 64; g = gm + i * 64;
        be = bem + i * 64; m = mm + i * 64; v = vm + i * 64;
    } else { w = wl; bb = bl; g = gl; be = bel; m = ml; v = vl; OC = 36; }

    uint32_t* out = wF + (size_t)(l * 9 + tap) * 2048;
    for (int e = threadIdx.x; e < 2048; e += blockDim.x) {
        int kc = e >> 9, nh = (e >> 8) & 1, lane = (e >> 3) & 31, r = e & 7;
        int nt = r >> 1, j = r & 1;
        int n = nh * 32 + nt * 8 + (lane >> 2);
        int k = kc * 16 + (lane & 3) * 2 + j * 8;
        float f0 = 0.f, f1 = 0.f;
        if (n < OC) {
            float sc = g[n] * rsqrtf(v[n] + 1e-5f);
            f0 = w[((size_t)n * 64 + k) * 9 + tap] * sc;
            f1 = w[((size_t)n * 64 + k + 1) * 9 + tap] * sc;
        }
        unsigned u0 = __half_as_ushort(__float2half_rn(f0));
        unsigned u1 = __half_as_ushort(__float2half_rn(f1));
        out[e] = u0 | (u1 << 16);
    }
    if (tap == 0)
        for (int oc = threadIdx.x; oc < 64; oc += blockDim.x) {
            float s = 0.f;
            if (oc < OC) {
                float sc = g[oc] * rsqrtf(v[oc] + 1e-5f);
                s = (bb[oc] - m[oc]) * sc + be[oc];
            }
            shiftT[l * 64 + oc] = s;
        }
}

// ---------------------------------------------------------------------------
// x [b][c][h][w] fp32 -> channel-last fp16 [b][h][w][c]
// ---------------------------------------------------------------------------
__global__ __launch_bounds__(128) void conv_input(
    const float* __restrict__ x, __half* __restrict__ XQ)
{
    const int w = threadIdx.x, r = blockIdx.x, b = blockIdx.y;
    unsigned hp[32];
    #pragma unroll
    for (int j = 0; j < 32; j++) {
        float f0 = x[((size_t)(b * 64 + 2 * j) * 128 + r) * 128 + w];
        float f1 = x[((size_t)(b * 64 + 2 * j + 1) * 128 + r) * 128 + w];
        hp[j] = (unsigned)__half_as_ushort(__float2half_rn(f0)) |
                ((unsigned)__half_as_ushort(__float2half_rn(f1)) << 16);
    }
    uint4* dh = (uint4*)(XQ + ((size_t)(b * 128 + r) * 128 + w) * 64);
    #pragma unroll
    for (int q = 0; q < 8; q++)
        dh[q] = make_uint4(hp[4*q], hp[4*q+1], hp[4*q+2], hp[4*q+3]);
}

// ---------------------------------------------------------------------------
// Warp-MMA conv layer, fp16, TWO image rows per CTA.
// CTA = (row-pair r2, batch b): output rows 2r2, 2r2+1; halo rows 2r2-1..2r2+2.
// 8 warps = 8 m32-stripes (px 0..255 row-major) x full n64.
// Per (tap,kc) per warp: 2 LDSM.x4 + 4 LDG.128(B) + 16 MMA  (0.375 L1/MMA).
// LAST=0: BN+tanh -> fp16 plane.  LAST=1 (64->36): + bcoef einsum.
// ---------------------------------------------------------------------------
template<int LAST>
__global__ __launch_bounds__(256, 2) void conv_mma_t(
    const __half* __restrict__ XQ, __half* __restrict__ YQ,
    const uint32_t* __restrict__ wFl, const float* __restrict__ shiftl,
    const float* __restrict__ bases, float* __restrict__ bco)
{
    extern __shared__ __align__(16) char sm[];
    const uint32_t alu = s2u(sm);
    const int tid = threadIdx.x, lane = tid & 31, wid = tid >> 5;
    const int lr = wid >> 2;            // local output row 0/1
    const int wb = (wid & 3) * 32;      // pixel-column base of the m32 stripe
    const int r2 = blockIdx.x, b = blockIdx.y;

    const uint32_t aoff = (uint32_t)(lane & 15) * 144u + (uint32_t)((lane >> 4) & 1) * 16u;

    if (tid < 64) ((float*)(sm + SH_OFF))[tid] = shiftl[tid];
    if (LAST && tid < 54) ((float*)(sm + BAS_OFF))[tid] = bases[tid];

    // zero halo edge pixels (halo pos 0 and 129) of all 4 slots
    {
        uint4 z = make_uint4(0, 0, 0, 0);
        for (int i = tid; i < 64; i += 256) {
            int slot = i >> 4, jj = (i >> 3) & 1, c = i & 7;
            *(uint4*)(sm + slot * A_SLOT + (jj ? 129 : 0) * 144 + c * 16) = z;
        }
        if (r2 == 0 || r2 == 63) {      // off-image halo row slot
            char* base = sm + (r2 ? 3 : 0) * A_SLOT;
            for (int i = tid; i < 1170; i += 256)
                *(uint4*)(base + i * 16) = z;
        }
    }

    // ---- async copies: 4 halo rows ----
    #pragma unroll
    for (int sl = 0; sl < 4; sl++) {
        int rimg = 2 * r2 - 1 + sl;
        if ((unsigned)rimg >= (unsigned)HH) continue;
        const char* src = (const char*)XQ + (size_t)(b * 128 + rimg) * 16384;
        uint32_t dstb = alu + (uint32_t)sl * A_SLOT;
        for (int i = tid; i < 1024; i += 256) {
            int px = i >> 3, c = i & 7;
            cp16(dstb + (uint32_t)(px + 1) * 144u + (uint32_t)c * 16u,
                 src + px * 128 + c * 16);
        }
    }
    asm volatile("cp.async.commit_group;" ::: "memory");
    asm volatile("cp.async.wait_group 0;" ::: "memory");
    __syncthreads();

    float cacc[2][8][4];
    #pragma unroll
    for (int mt = 0; mt < 2; mt++)
        #pragma unroll
        for (int nt = 0; nt < 8; nt++)
            #pragma unroll
            for (int j = 0; j < 4; j++) cacc[mt][nt][j] = 0.f;

    // ---- mainloop: 9 taps x 4 kc ----
    #pragma unroll 1
    for (int tap = 0; tap < 9; tap++) {
        const int dy = tap / 3, dx = tap % 3;
        // slot = lr + dy; pixel w tap dx reads halo position w+dx
        const uint32_t aB = alu + (uint32_t)(lr + dy) * A_SLOT +
                            (uint32_t)(wb + dx) * 144u;
        #pragma unroll
        for (int kc = 0; kc < 4; kc++) {
            const uint32_t kb = (uint32_t)kc * 32u;
            uint32_t ah[2][4];
            ldsm4(ah[0], aB + kb + aoff);
            ldsm4(ah[1], aB + 16u * 144u + kb + aoff);

            const uint4* f0 = (const uint4*)(wFl +
                ((((size_t)tap * 4 + kc) * 2 + 0) * 32 + lane) * 8);
            const uint4* f1 = (const uint4*)(wFl +
                ((((size_t)tap * 4 + kc) * 2 + 1) * 32 + lane) * 8);
            uint4 q0 = f0[0], q1 = f0[1], q2 = f1[0], q3 = f1[1];
            uint32_t bh[8][2];
            bh[0][0] = q0.x; bh[0][1] = q0.y; bh[1][0] = q0.z; bh[1][1] = q0.w;
            bh[2][0] = q1.x; bh[2][1] = q1.y; bh[3][0] = q1.z; bh[3][1] = q1.w;
            bh[4][0] = q2.x; bh[4][1] = q2.y; bh[5][0] = q2.z; bh[5][1] = q2.w;
            bh[6][0] = q3.x; bh[6][1] = q3.y; bh[7][0] = q3.z; bh[7][1] = q3.w;

            #pragma unroll
            for (int mt = 0; mt < 2; mt++)
                #pragma unroll
                for (int nt = 0; nt < 8; nt++)
                    mma16816(cacc[mt][nt], ah[mt], bh[nt]);
        }
    }
    __syncthreads();   // A region now reusable as acc

    // ---- accumulators -> smem [256 px][66-stride fp32] ----
    float* acc = (float*)sm;
    {
        const int rbase = (lr * 4 + (wb >> 5)) * 32 + (lane >> 2);  // = wid*32 + lane/4
        const int cb = (lane & 3) * 2;
        #pragma unroll
        for (int mt = 0; mt < 2; mt++)
            #pragma unroll
            for (int nt = 0; nt < 8; nt++) {
                int row = rbase + mt * 16, col = cb + nt * 8;
                *(float2*)&acc[row * 66 + col] =
                    make_float2(cacc[mt][nt][0], cacc[mt][nt][1]);
                *(float2*)&acc[(row + 8) * 66 + col] =
                    make_float2(cacc[mt][nt][2], cacc[mt][nt][3]);
            }
    }
    __syncthreads();

    if (!LAST) {
        // ---- epilogue: one thread per pixel, tanh -> fp16 plane ----
        const int px = tid;
        const int rowg = 2 * r2 + (px >> 7), w = px & 127;
        const float* shp = (const float*)(sm + SH_OFF);
        const float* ap = acc + px * 66;
        unsigned hp[32];
        #pragma unroll
        for (int j = 0; j < 32; j++) {
            float2 vv = *(const float2*)&ap[2 * j];
            float t0 = tanh_fast(vv.x + shp[2 * j]);
            float t1 = tanh_fast(vv.y + shp[2 * j + 1]);
            hp[j] = (unsigned)__half_as_ushort(__float2half_rn(t0)) |
                    ((unsigned)__half_as_ushort(__float2half_rn(t1)) << 16);
        }
        uint4* dh = (uint4*)(YQ + ((size_t)(b * 128 + rowg) * 128 + w) * 64);
        #pragma unroll
        for (int q = 0; q < 8; q++)
            dh[q] = make_uint4(hp[4*q], hp[4*q+1], hp[4*q+2], hp[4*q+3]);
    } else {
        // ---- epilogue: one thread per pixel, tanh(36) + bcoef einsum ----
        const int px = tid;
        const int rowg = 2 * r2 + (px >> 7), w = px & 127;
        const int pixg = rowg * 128 + w;
        const float* shp = (const float*)(sm + SH_OFF);
        const float* basS = (const float*)(sm + BAS_OFF);
        const float* ap = acc + px * 66;
        float hm[36];
        #pragma unroll
        for (int oc = 0; oc < 36; oc++)
            hm[oc] = tanh_fast(ap[oc] + shp[oc]);
        #pragma unroll
        for (int m = 0; m < 6; m++)
            #pragma unroll
            for (int l = 0; l < 9; l++) {
                float s = 0.f;
                #pragma unroll
                for (int k = 0; k < 6; k++)
                    s = fmaf(hm[m * 6 + k], basS[k * 9 + l], s);
                bco[((size_t)(b * 6 + m) * 9 + l) * HW + pixg] = s;
            }
    }
}

// ---------------------------------------------------------------------------
__global__ __launch_bounds__(256) void dynconv(
    const float* __restrict__ x, const float* __restrict__ bco,
    float* __restrict__ out)
{
    const int b = blockIdx.y;
    const int pix = blockIdx.x * 256 + threadIdx.x;
    const int h = pix >> 7, w = pix & 127;

    float bc[54];
    const float* bcb = bco + (size_t)b * 54 * HW + pix;
    #pragma unroll
    for (int i = 0; i < 54; i++) bc[i] = bcb[(size_t)i * HW];

    bool ok[9]; int off[9];
    #pragma unroll
    for (int dy = 0; dy < 3; dy++)
        #pragma unroll
        for (int dx = 0; dx < 3; dx++) {
            int k = dy * 3 + dx;
            int hh = h + dy - 1, ww = w + dx - 1;
            ok[k] = ((unsigned)hh < HH) && ((unsigned)ww < WWID);
            off[k] = hh * WWID + ww;
        }

    const float* xb = x + (size_t)b * CIN * HW;
    float* ob = out + (size_t)b * (CIN * 6) * HW + pix;

    for (int c = 0; c < CIN; c++) {
        const float* xc = xb + c * HW;
        float v[9];
        #pragma unroll
        for (int k = 0; k < 9; k++) v[k] = ok[k] ? __ldg(xc + off[k]) : 0.f;
        #pragma unroll
        for (int m = 0; m < 6; m++) {
            float s = 0.f;
            #pragma unroll
            for (int k = 0; k < 9; k++) s = fmaf(bc[m * 9 + k], v[k], s);
            ob[(size_t)(c * 6 + m) * HW] = s;
        }
    }
}

// ---------------------------------------------------------------------------
extern "C" void kernel_launch(void* const* d_in, const int* in_sizes, int n_in,
                              void* d_out, int out_size) {
    const float* x    = (const float*)d_in[0];
    const float* w0   = (const float*)d_in[1];
    const float* b0   = (const float*)d_in[2];
    const float* g0   = (const float*)d_in[3];
    const float* be0  = (const float*)d_in[4];
    const float* m0   = (const float*)d_in[5];
    const float* v0   = (const float*)d_in[6];
    const float* wm   = (const float*)d_in[7];
    const float* bm   = (const float*)d_in[8];
    const float* gm   = (const float*)d_in[9];
    const float* bem  = (const float*)d_in[10];
    const float* mm   = (const float*)d_in[11];
    const float* vm   = (const float*)d_in[12];
    const float* wl   = (const float*)d_in[13];
    const float* bl   = (const float*)d_in[14];
    const float* gl   = (const float*)d_in[15];
    const float* bel  = (const float*)d_in[16];
    const float* ml   = (const float*)d_in[17];
    const float* vl   = (const float*)d_in[18];
    const float* bases= (const float*)d_in[19];

    __half *q0, *q1;
    float *bco, *shiftT;
    uint32_t* wF;
    cudaGetSymbolAddress((void**)&q0, g_q0);
    cudaGetSymbolAddress((void**)&q1, g_q1);
    cudaGetSymbolAddress((void**)&bco,  g_bcoef);
    cudaGetSymbolAddress((void**)&wF,   g_wF);
    cudaGetSymbolAddress((void**)&shiftT, g_shiftT);

    cudaFuncSetAttribute(conv_mma_t<0>, cudaFuncAttributeMaxDynamicSharedMemorySize, SMEM_BYTES);
    cudaFuncSetAttribute(conv_mma_t<1>, cudaFuncAttributeMaxDynamicSharedMemorySize, SMEM_BYTES);

    dim3 pgrd(9, 7);
    prep_weights<<<pgrd, 256>>>(w0, b0, g0, be0, m0, v0,
                                wm, bm, gm, bem, mm, vm,
                                wl, bl, gl, bel, ml, vl, wF, shiftT);

    dim3 sgrd(128, NBATCH);
    conv_input<<<sgrd, 128>>>(x, q0);

    dim3 cgrd(64, NBATCH);   // 64 row-pairs per batch
    __half* buf[2] = { q0, q1 };
    for (int l = 0; l < 6; l++) {
        conv_mma_t<0><<<cgrd, 256, SMEM_BYTES>>>(
            buf[l & 1], buf[(l + 1) & 1],
            wF + (size_t)l * 9 * 2048, shiftT + l * 64, nullptr, nullptr);
    }
    // last layer (64->36) + bcoef, reads layer-5 output plane (q0)
    conv_mma_t<1><<<cgrd, 256, SMEM_BYTES>>>(
        q0, nullptr,
        wF + (size_t)6 * 9 * 2048, shiftT + 6 * 64, bases, bco);

    dim3 grd2(HW / 256, NBATCH);
    dynconv<<<grd2, 256>>>(x, bco, (float*)d_out);
}

// round 14
// speedup vs baseline: 1.2489x; 1.0440x over previous
#include <cuda_runtime.h>
#include <cuda_bf16.h>
#include <cuda_fp16.h>
#include <cstdint>

#define HH 128
#define WWID 128
#define NBATCH 8
#define CIN 64
#define HW (HH*WWID)

// ---------------- device scratch ----------------
__device__ __half g_q0[NBATCH * HW * CIN];     // channel-last fp16 plane
__device__ __half g_q1[NBATCH * HW * CIN];
__device__ float g_bcoef[NBATCH * 54 * HW];
__device__ uint32_t g_wF[7 * 9 * 2048];        // [l][tap][kc][nh][lane][8] fragment regs
__device__ float g_shiftT[7 * 64];

// smem (bytes): A halo 4 slots (rows 2r-1..2r+2) of 130px*144B = 18720 -> 74880
// shift @74880 (256B), bases @75136 (216B).
// acc (256*66*4 = 67584) reuses the A region after the mainloop.
#define A_SLOT 18720u
#define SH_OFF 74880u
#define BAS_OFF 75136u
#define SMEM_BYTES 75392

__device__ __forceinline__ float tanh_fast(float x) {
    float a = fminf(fmaxf(x, -9.f), 9.f);
    float e = __expf(2.f * a);
    return __fdividef(e - 1.f, e + 1.f);
}
__device__ __forceinline__ void cp16(uint32_t dst, const void* src) {
    asm volatile("cp.async.cg.shared.global [%0], [%1], 16;" :: "r"(dst), "l"(src));
}
__device__ __forceinline__ uint32_t s2u(const void* p) {
    return (uint32_t)__cvta_generic_to_shared(p);
}
__device__ __forceinline__ void ldsm4(uint32_t* a, uint32_t addr) {
    asm volatile("ldmatrix.sync.aligned.m8n8.x4.shared.b16 {%0,%1,%2,%3}, [%4];"
                 : "=r"(a[0]), "=r"(a[1]), "=r"(a[2]), "=r"(a[3]) : "r"(addr));
}
__device__ __forceinline__ void mma16816(float* c, const uint32_t* a, const uint32_t* b) {
    asm volatile("mma.sync.aligned.m16n8k16.row.col.f32.f16.f16.f32 "
                 "{%0,%1,%2,%3}, {%4,%5,%6,%7}, {%8,%9}, {%0,%1,%2,%3};"
                 : "+f"(c[0]), "+f"(c[1]), "+f"(c[2]), "+f"(c[3])
                 : "r"(a[0]), "r"(a[1]), "r"(a[2]), "r"(a[3]), "r"(b[0]), "r"(b[1]));
}

// ---------------------------------------------------------------------------
// Prep: BN-fold weights -> fp16 per-lane MMA fragments.
// reg r = nt*2 + j:  n = nh*32 + nt*8 + lane/4,  k = kc*16 + (lane%4)*2 + j*8
// Layers 0..5: 64 oc. Layer 6 (last): 36 oc zero-padded to 64.
// ---------------------------------------------------------------------------
__global__ void prep_weights(
    const float* __restrict__ w0, const float* __restrict__ b0,
    const float* __restrict__ g0, const float* __restrict__ be0,
    const float* __restrict__ m0, const float* __restrict__ v0,
    const float* __restrict__ wm, const float* __restrict__ bm,
    const float* __restrict__ gm, const float* __restrict__ bem,
    const float* __restrict__ mm, const float* __restrict__ vm,
    const float* __restrict__ wl, const float* __restrict__ bl,
    const float* __restrict__ gl, const float* __restrict__ bel,
    const float* __restrict__ ml, const float* __restrict__ vl,
    uint32_t* __restrict__ wF, float* __restrict__ shiftT)
{
    const int tap = blockIdx.x, l = blockIdx.y;
    const float *w, *bb, *g, *be, *m, *v;
    int OC = 64;
    if (l == 0)      { w = w0; bb = b0; g = g0; be = be0; m = m0; v = v0; }
    else if (l <= 5) {
        int i = l - 1;
        w = wm + (size_t)i * 64 * 64 * 9; bb = bm + i * 64; g = gm + i * 64;
        be = bem + i * 64; m = mm + i * 64; v = vm + i * 64;
    } else { w = wl; bb = bl; g = gl; be = bel; m = ml; v = vl; OC = 36; }

    uint32_t* out = wF + (size_t)(l * 9 + tap) * 2048;
    for (int e = threadIdx.x; e < 2048; e += blockDim.x) {
        int kc = e >> 9, nh = (e >> 8) & 1, lane = (e >> 3) & 31, r = e & 7;
        int nt = r >> 1, j = r & 1;
        int n = nh * 32 + nt * 8 + (lane >> 2);
        int k = kc * 16 + (lane & 3) * 2 + j * 8;
        float f0 = 0.f, f1 = 0.f;
        if (n < OC) {
            float sc = g[n] * rsqrtf(v[n] + 1e-5f);
            f0 = w[((size_t)n * 64 + k) * 9 + tap] * sc;
            f1 = w[((size_t)n * 64 + k + 1) * 9 + tap] * sc;
        }
        unsigned u0 = __half_as_ushort(__float2half_rn(f0));
        unsigned u1 = __half_as_ushort(__float2half_rn(f1));
        out[e] = u0 | (u1 << 16);
    }
    if (tap == 0)
        for (int oc = threadIdx.x; oc < 64; oc += blockDim.x) {
            float s = 0.f;
            if (oc < OC) {
                float sc = g[oc] * rsqrtf(v[oc] + 1e-5f);
                s = (bb[oc] - m[oc]) * sc + be[oc];
            }
            shiftT[l * 64 + oc] = s;
        }
}

// ---------------------------------------------------------------------------
// x [b][c][h][w] fp32 -> channel-last fp16 [b][h][w][c]
// ---------------------------------------------------------------------------
__global__ __launch_bounds__(128) void conv_input(
    const float* __restrict__ x, __half* __restrict__ XQ)
{
    const int w = threadIdx.x, r = blockIdx.x, b = blockIdx.y;
    unsigned hp[32];
    #pragma unroll
    for (int j = 0; j < 32; j++) {
        float f0 = x[((size_t)(b * 64 + 2 * j) * 128 + r) * 128 + w];
        float f1 = x[((size_t)(b * 64 + 2 * j + 1) * 128 + r) * 128 + w];
        hp[j] = (unsigned)__half_as_ushort(__float2half_rn(f0)) |
                ((unsigned)__half_as_ushort(__float2half_rn(f1)) << 16);
    }
    uint4* dh = (uint4*)(XQ + ((size_t)(b * 128 + r) * 128 + w) * 64);
    #pragma unroll
    for (int q = 0; q < 8; q++)
        dh[q] = make_uint4(hp[4*q], hp[4*q+1], hp[4*q+2], hp[4*q+3]);
}

// ---------------------------------------------------------------------------
// Warp-MMA conv layer, fp16, TWO image rows per CTA.
// CTA = (row-pair r2, batch b). 8 warps = 8 m32-stripes x n64 (n40 for LAST).
// Tap loop fully unrolled so ptxas can hoist B LDGs / LDSMs into MMA shadow.
// LAST=0: NT=8 (n64), BN+tanh -> fp16 plane.
// LAST=1: NT=5 (n40 covers 36 oc), + bcoef einsum.
// ---------------------------------------------------------------------------
template<int LAST>
__global__ __launch_bounds__(256, 2) void conv_mma_t(
    const __half* __restrict__ XQ, __half* __restrict__ YQ,
    const uint32_t* __restrict__ wFl, const float* __restrict__ shiftl,
    const float* __restrict__ bases, float* __restrict__ bco)
{
    constexpr int NT = LAST ? 5 : 8;
    extern __shared__ __align__(16) char sm[];
    const uint32_t alu = s2u(sm);
    const int tid = threadIdx.x, lane = tid & 31, wid = tid >> 5;
    const int lr = wid >> 2;            // local output row 0/1
    const int wb = (wid & 3) * 32;      // pixel-column base of the m32 stripe
    const int r2 = blockIdx.x, b = blockIdx.y;

    const uint32_t aoff = (uint32_t)(lane & 15) * 144u + (uint32_t)((lane >> 4) & 1) * 16u;

    if (tid < 64) ((float*)(sm + SH_OFF))[tid] = shiftl[tid];
    if (LAST && tid < 54) ((float*)(sm + BAS_OFF))[tid] = bases[tid];

    // zero halo edge pixels (halo pos 0 and 129) of all 4 slots
    {
        uint4 z = make_uint4(0, 0, 0, 0);
        for (int i = tid; i < 64; i += 256) {
            int slot = i >> 4, jj = (i >> 3) & 1, c = i & 7;
            *(uint4*)(sm + slot * A_SLOT + (jj ? 129 : 0) * 144 + c * 16) = z;
        }
        if (r2 == 0 || r2 == 63) {      // off-image halo row slot
            char* base = sm + (r2 ? 3 : 0) * A_SLOT;
            for (int i = tid; i < 1170; i += 256)
                *(uint4*)(base + i * 16) = z;
        }
    }

    // ---- async copies: 4 halo rows ----
    #pragma unroll
    for (int sl = 0; sl < 4; sl++) {
        int rimg = 2 * r2 - 1 + sl;
        if ((unsigned)rimg >= (unsigned)HH) continue;
        const char* src = (const char*)XQ + (size_t)(b * 128 + rimg) * 16384;
        uint32_t dstb = alu + (uint32_t)sl * A_SLOT;
        for (int i = tid; i < 1024; i += 256) {
            int px = i >> 3, c = i & 7;
            cp16(dstb + (uint32_t)(px + 1) * 144u + (uint32_t)c * 16u,
                 src + px * 128 + c * 16);
        }
    }
    asm volatile("cp.async.commit_group;" ::: "memory");
    asm volatile("cp.async.wait_group 0;" ::: "memory");
    __syncthreads();

    float cacc[2][NT][4];
    #pragma unroll
    for (int mt = 0; mt < 2; mt++)
        #pragma unroll
        for (int nt = 0; nt < NT; nt++)
            #pragma unroll
            for (int j = 0; j < 4; j++) cacc[mt][nt][j] = 0.f;

    // ---- mainloop: 9 taps x 4 kc, fully unrolled ----
    #pragma unroll
    for (int dy = 0; dy < 3; dy++)
    #pragma unroll
    for (int dx = 0; dx < 3; dx++) {
        const int tap = dy * 3 + dx;
        const uint32_t aB = alu + (uint32_t)(lr + dy) * A_SLOT +
                            (uint32_t)(wb + dx) * 144u;
        #pragma unroll
        for (int kc = 0; kc < 4; kc++) {
            const uint32_t kb = (uint32_t)kc * 32u;
            uint32_t ah[2][4];
            ldsm4(ah[0], aB + kb + aoff);
            ldsm4(ah[1], aB + 16u * 144u + kb + aoff);

            const uint32_t* fb = wFl + (((size_t)tap * 4 + kc) * 2) * 256 + lane * 8;
            uint32_t bh[2 * NT];
            if (!LAST) {
                uint4 q0 = *(const uint4*)fb;
                uint4 q1 = *(const uint4*)(fb + 4);
                uint4 q2 = *(const uint4*)(fb + 256);
                uint4 q3 = *(const uint4*)(fb + 260);
                bh[0] = q0.x; bh[1] = q0.y; bh[2] = q0.z; bh[3] = q0.w;
                bh[4] = q1.x; bh[5] = q1.y; bh[6] = q1.z; bh[7] = q1.w;
                bh[8] = q2.x; bh[9] = q2.y; bh[10] = q2.z; bh[11] = q2.w;
                bh[12] = q3.x; bh[13] = q3.y; bh[14] = q3.z; bh[15] = q3.w;
            } else {
                uint4 q0 = *(const uint4*)fb;
                uint4 q1 = *(const uint4*)(fb + 4);
                uint2 q2 = *(const uint2*)(fb + 256);
                bh[0] = q0.x; bh[1] = q0.y; bh[2] = q0.z; bh[3] = q0.w;
                bh[4] = q1.x; bh[5] = q1.y; bh[6] = q1.z; bh[7] = q1.w;
                bh[8] = q2.x; bh[9] = q2.y;
            }

            #pragma unroll
            for (int mt = 0; mt < 2; mt++)
                #pragma unroll
                for (int nt = 0; nt < NT; nt++)
                    mma16816(cacc[mt][nt], ah[mt], &bh[2 * nt]);
        }
    }
    __syncthreads();   // A region now reusable as acc

    // ---- accumulators -> smem [256 px][66-stride fp32] ----
    float* acc = (float*)sm;
    {
        const int rbase = wid * 32 + (lane >> 2);
        const int cb = (lane & 3) * 2;
        #pragma unroll
        for (int mt = 0; mt < 2; mt++)
            #pragma unroll
            for (int nt = 0; nt < NT; nt++) {
                int row = rbase + mt * 16, col = cb + nt * 8;
                *(float2*)&acc[row * 66 + col] =
                    make_float2(cacc[mt][nt][0], cacc[mt][nt][1]);
                *(float2*)&acc[(row + 8) * 66 + col] =
                    make_float2(cacc[mt][nt][2], cacc[mt][nt][3]);
            }
    }
    __syncthreads();

    if (!LAST) {
        // ---- epilogue: one thread per pixel, tanh -> fp16 plane ----
        const int px = tid;
        const int rowg = 2 * r2 + (px >> 7), w = px & 127;
        const float* shp = (const float*)(sm + SH_OFF);
        const float* ap = acc + px * 66;
        unsigned hp[32];
        #pragma unroll
        for (int j = 0; j < 32; j++) {
            float2 vv = *(const float2*)&ap[2 * j];
            float t0 = tanh_fast(vv.x + shp[2 * j]);
            float t1 = tanh_fast(vv.y + shp[2 * j + 1]);
            hp[j] = (unsigned)__half_as_ushort(__float2half_rn(t0)) |
                    ((unsigned)__half_as_ushort(__float2half_rn(t1)) << 16);
        }
        uint4* dh = (uint4*)(YQ + ((size_t)(b * 128 + rowg) * 128 + w) * 64);
        #pragma unroll
        for (int q = 0; q < 8; q++)
            dh[q] = make_uint4(hp[4*q], hp[4*q+1], hp[4*q+2], hp[4*q+3]);
    } else {
        // ---- epilogue: one thread per pixel, tanh(36) + bcoef einsum ----
        const int px = tid;
        const int rowg = 2 * r2 + (px >> 7), w = px & 127;
        const int pixg = rowg * 128 + w;
        const float* shp = (const float*)(sm + SH_OFF);
        const float* basS = (const float*)(sm + BAS_OFF);
        const float* ap = acc + px * 66;
        float hm[36];
        #pragma unroll
        for (int oc = 0; oc < 36; oc++)
            hm[oc] = tanh_fast(ap[oc] + shp[oc]);
        #pragma unroll
        for (int m = 0; m < 6; m++)
            #pragma unroll
            for (int l = 0; l < 9; l++) {
                float s = 0.f;
                #pragma unroll
                for (int k = 0; k < 6; k++)
                    s = fmaf(hm[m * 6 + k], basS[k * 9 + l], s);
                bco[((size_t)(b * 6 + m) * 9 + l) * HW + pixg] = s;
            }
    }
}

// ---------------------------------------------------------------------------
__global__ __launch_bounds__(256) void dynconv(
    const float* __restrict__ x, const float* __restrict__ bco,
    float* __restrict__ out)
{
    const int b = blockIdx.y;
    const int pix = blockIdx.x * 256 + threadIdx.x;
    const int h = pix >> 7, w = pix & 127;

    float bc[54];
    const float* bcb = bco + (size_t)b * 54 * HW + pix;
    #pragma unroll
    for (int i = 0; i < 54; i++) bc[i] = __ldcs(bcb + (size_t)i * HW);

    bool ok[9]; int off[9];
    #pragma unroll
    for (int dy = 0; dy < 3; dy++)
        #pragma unroll
        for (int dx = 0; dx < 3; dx++) {
            int k = dy * 3 + dx;
            int hh = h + dy - 1, ww = w + dx - 1;
            ok[k] = ((unsigned)hh < HH) && ((unsigned)ww < WWID);
            off[k] = hh * WWID + ww;
        }

    const float* xb = x + (size_t)b * CIN * HW;
    float* ob = out + (size_t)b * (CIN * 6) * HW + pix;

    for (int c = 0; c < CIN; c++) {
        const float* xc = xb + c * HW;
        float v[9];
        #pragma unroll
        for (int k = 0; k < 9; k++) v[k] = ok[k] ? __ldg(xc + off[k]) : 0.f;
        #pragma unroll
        for (int m = 0; m < 6; m++) {
            float s = 0.f;
            #pragma unroll
            for (int k = 0; k < 9; k++) s = fmaf(bc[m * 9 + k], v[k], s);
            __stcs(ob + (size_t)(c * 6 + m) * HW, s);
        }
    }
}

// ---------------------------------------------------------------------------
extern "C" void kernel_launch(void* const* d_in, const int* in_sizes, int n_in,
                              void* d_out, int out_size) {
    const float* x    = (const float*)d_in[0];
    const float* w0   = (const float*)d_in[1];
    const float* b0   = (const float*)d_in[2];
    const float* g0   = (const float*)d_in[3];
    const float* be0  = (const float*)d_in[4];
    const float* m0   = (const float*)d_in[5];
    const float* v0   = (const float*)d_in[6];
    const float* wm   = (const float*)d_in[7];
    const float* bm   = (const float*)d_in[8];
    const float* gm   = (const float*)d_in[9];
    const float* bem  = (const float*)d_in[10];
    const float* mm   = (const float*)d_in[11];
    const float* vm   = (const float*)d_in[12];
    const float* wl   = (const float*)d_in[13];
    const float* bl   = (const float*)d_in[14];
    const float* gl   = (const float*)d_in[15];
    const float* bel  = (const float*)d_in[16];
    const float* ml   = (const float*)d_in[17];
    const float* vl   = (const float*)d_in[18];
    const float* bases= (const float*)d_in[19];

    __half *q0, *q1;
    float *bco, *shiftT;
    uint32_t* wF;
    cudaGetSymbolAddress((void**)&q0, g_q0);
    cudaGetSymbolAddress((void**)&q1, g_q1);
    cudaGetSymbolAddress((void**)&bco,  g_bcoef);
    cudaGetSymbolAddress((void**)&wF,   g_wF);
    cudaGetSymbolAddress((void**)&shiftT, g_shiftT);

    cudaFuncSetAttribute(conv_mma_t<0>, cudaFuncAttributeMaxDynamicSharedMemorySize, SMEM_BYTES);
    cudaFuncSetAttribute(conv_mma_t<1>, cudaFuncAttributeMaxDynamicSharedMemorySize, SMEM_BYTES);

    dim3 pgrd(9, 7);
    prep_weights<<<pgrd, 256>>>(w0, b0, g0, be0, m0, v0,
                                wm, bm, gm, bem, mm, vm,
                                wl, bl, gl, bel, ml, vl, wF, shiftT);

    dim3 sgrd(128, NBATCH);
    conv_input<<<sgrd, 128>>>(x, q0);

    dim3 cgrd(64, NBATCH);   // 64 row-pairs per batch
    __half* buf[2] = { q0, q1 };
    for (int l = 0; l < 6; l++) {
        conv_mma_t<0><<<cgrd, 256, SMEM_BYTES>>>(
            buf[l & 1], buf[(l + 1) & 1],
            wF + (size_t)l * 9 * 2048, shiftT + l * 64, nullptr, nullptr);
    }
    // last layer (64->36, n40 tiles) + bcoef, reads layer-5 output plane (q0)
    conv_mma_t<1><<<cgrd, 256, SMEM_BYTES>>>(
        q0, nullptr,
        wF + (size_t)6 * 9 * 2048, shiftT + 6 * 64, bases, bco);

    dim3 grd2(HW / 256, NBATCH);
    dynconv<<<grd2, 256>>>(x, bco, (float*)d_out);
}

// round 15
// speedup vs baseline: 1.3488x; 1.0800x over previous
#include <cuda_runtime.h>
#include <cuda_bf16.h>
#include <cuda_fp16.h>
#include <cstdint>

#define HH 128
#define WWID 128
#define NBATCH 8
#define CIN 64
#define HW (HH*WWID)

// ---------------- device scratch ----------------
__device__ __half g_q0[NBATCH * HW * CIN];     // channel-last fp16 plane
__device__ __half g_q1[NBATCH * HW * CIN];
__device__ float g_bcoef[NBATCH * 54 * HW];
__device__ uint32_t g_wF[7 * 9 * 2048];        // [l][tap][kc][q][lane][4] coalesced blocks
__device__ float g_shiftT[7 * 64];

// smem (bytes): A halo 4 slots (rows 2r-1..2r+2) of 130px*144B = 18720 -> 74880
// shift @74880 (256B), bases @75136 (216B).
// acc (256*66*4 = 67584) reuses the A region after the mainloop.
#define A_SLOT 18720u
#define SH_OFF 74880u
#define BAS_OFF 75136u
#define SMEM_BYTES 75392

__device__ __forceinline__ float tanh_fast(float x) {
    float a = fminf(fmaxf(x, -9.f), 9.f);
    float e = __expf(2.f * a);
    return __fdividef(e - 1.f, e + 1.f);
}
__device__ __forceinline__ void cp16(uint32_t dst, const void* src) {
    asm volatile("cp.async.cg.shared.global [%0], [%1], 16;" :: "r"(dst), "l"(src));
}
__device__ __forceinline__ uint32_t s2u(const void* p) {
    return (uint32_t)__cvta_generic_to_shared(p);
}
__device__ __forceinline__ void ldsm4(uint32_t* a, uint32_t addr) {
    asm volatile("ldmatrix.sync.aligned.m8n8.x4.shared.b16 {%0,%1,%2,%3}, [%4];"
                 : "=r"(a[0]), "=r"(a[1]), "=r"(a[2]), "=r"(a[3]) : "r"(addr));
}
__device__ __forceinline__ void mma16816(float* c, const uint32_t* a, const uint32_t* b) {
    asm volatile("mma.sync.aligned.m16n8k16.row.col.f32.f16.f16.f32 "
                 "{%0,%1,%2,%3}, {%4,%5,%6,%7}, {%8,%9}, {%0,%1,%2,%3};"
                 : "+f"(c[0]), "+f"(c[1]), "+f"(c[2]), "+f"(c[3])
                 : "r"(a[0]), "r"(a[1]), "r"(a[2]), "r"(a[3]), "r"(b[0]), "r"(b[1]));
}

// ---------------------------------------------------------------------------
// Prep: BN-fold weights -> fp16 per-lane MMA fragments, COALESCED layout.
// Block q (0..3) of 512B holds regs for (nh = q>>1, r = (q&1)*4 + i), i=0..3:
//   out[kc*512 + q*128 + lane*4 + i]
// Fragment value: r = nt*2+j; n = nh*32 + nt*8 + lane/4; k = kc*16 + (lane%4)*2 + j*8
// Layers 0..5: 64 oc. Layer 6 (last): 36 oc zero-padded.
// ---------------------------------------------------------------------------
__global__ void prep_weights(
    const float* __restrict__ w0, const float* __restrict__ b0,
    const float* __restrict__ g0, const float* __restrict__ be0,
    const float* __restrict__ m0, const float* __restrict__ v0,
    const float* __restrict__ wm, const float* __restrict__ bm,
    const float* __restrict__ gm, const float* __restrict__ bem,
    const float* __restrict__ mm, const float* __restrict__ vm,
    const float* __restrict__ wl, const float* __restrict__ bl,
    const float* __restrict__ gl, const float* __restrict__ bel,
    const float* __restrict__ ml, const float* __restrict__ vl,
    uint32_t* __restrict__ wF, float* __restrict__ shiftT)
{
    const int tap = blockIdx.x, l = blockIdx.y;
    const float *w, *bb, *g, *be, *m, *v;
    int OC = 64;
    if (l == 0)      { w = w0; bb = b0; g = g0; be = be0; m = m0; v = v0; }
    else if (l <= 5) {
        int i = l - 1;
        w = wm + (size_t)i * 64 * 64 * 9; bb = bm + i * 64; g = gm + i * 64;
        be = bem + i * 64; m = mm + i * 64; v = vm + i * 64;
    } else { w = wl; bb = bl; g = gl; be = bel; m = ml; v = vl; OC = 36; }

    uint32_t* out = wF + (size_t)(l * 9 + tap) * 2048;
    for (int e = threadIdx.x; e < 2048; e += blockDim.x) {
        int kc = e >> 9, q = (e >> 7) & 3, lane = (e >> 2) & 31, i = e & 3;
        int nh = q >> 1, r = (q & 1) * 4 + i;
        int nt = r >> 1, j = r & 1;
        int n = nh * 32 + nt * 8 + (lane >> 2);
        int k = kc * 16 + (lane & 3) * 2 + j * 8;
        float f0 = 0.f, f1 = 0.f;
        if (n < OC) {
            float sc = g[n] * rsqrtf(v[n] + 1e-5f);
            f0 = w[((size_t)n * 64 + k) * 9 + tap] * sc;
            f1 = w[((size_t)n * 64 + k + 1) * 9 + tap] * sc;
        }
        unsigned u0 = __half_as_ushort(__float2half_rn(f0));
        unsigned u1 = __half_as_ushort(__float2half_rn(f1));
        out[e] = u0 | (u1 << 16);
    }
    if (tap == 0)
        for (int oc = threadIdx.x; oc < 64; oc += blockDim.x) {
            float s = 0.f;
            if (oc < OC) {
                float sc = g[oc] * rsqrtf(v[oc] + 1e-5f);
                s = (bb[oc] - m[oc]) * sc + be[oc];
            }
            shiftT[l * 64 + oc] = s;
        }
}

// ---------------------------------------------------------------------------
// x [b][c][h][w] fp32 -> channel-last fp16 [b][h][w][c]
// ---------------------------------------------------------------------------
__global__ __launch_bounds__(128) void conv_input(
    const float* __restrict__ x, __half* __restrict__ XQ)
{
    const int w = threadIdx.x, r = blockIdx.x, b = blockIdx.y;
    unsigned hp[32];
    #pragma unroll
    for (int j = 0; j < 32; j++) {
        float f0 = x[((size_t)(b * 64 + 2 * j) * 128 + r) * 128 + w];
        float f1 = x[((size_t)(b * 64 + 2 * j + 1) * 128 + r) * 128 + w];
        hp[j] = (unsigned)__half_as_ushort(__float2half_rn(f0)) |
                ((unsigned)__half_as_ushort(__float2half_rn(f1)) << 16);
    }
    uint4* dh = (uint4*)(XQ + ((size_t)(b * 128 + r) * 128 + w) * 64);
    #pragma unroll
    for (int q = 0; q < 8; q++)
        dh[q] = make_uint4(hp[4*q], hp[4*q+1], hp[4*q+2], hp[4*q+3]);
}

// ---------------------------------------------------------------------------
// Warp-MMA conv layer, fp16, TWO image rows per CTA.
// CTA = (row-pair r2, batch b). 8 warps = 8 m32-stripes x n64 (n40 for LAST).
// B fragments: coalesced 512B blocks -> each LDG.128 = 4 L1 wavefronts.
// LAST=0: NT=8 (n64), BN+tanh -> fp16 plane.
// LAST=1: NT=5 (n40 covers 36 oc), + bcoef einsum.
// ---------------------------------------------------------------------------
template<int LAST>
__global__ __launch_bounds__(256, 2) void conv_mma_t(
    const __half* __restrict__ XQ, __half* __restrict__ YQ,
    const uint32_t* __restrict__ wFl, const float* __restrict__ shiftl,
    const float* __restrict__ bases, float* __restrict__ bco)
{
    constexpr int NT = LAST ? 5 : 8;
    extern __shared__ __align__(16) char sm[];
    const uint32_t alu = s2u(sm);
    const int tid = threadIdx.x, lane = tid & 31, wid = tid >> 5;
    const int lr = wid >> 2;            // local output row 0/1
    const int wb = (wid & 3) * 32;      // pixel-column base of the m32 stripe
    const int r2 = blockIdx.x, b = blockIdx.y;

    const uint32_t aoff = (uint32_t)(lane & 15) * 144u + (uint32_t)((lane >> 4) & 1) * 16u;

    if (tid < 64) ((float*)(sm + SH_OFF))[tid] = shiftl[tid];
    if (LAST && tid < 54) ((float*)(sm + BAS_OFF))[tid] = bases[tid];

    // zero halo edge pixels (halo pos 0 and 129) of all 4 slots
    {
        uint4 z = make_uint4(0, 0, 0, 0);
        for (int i = tid; i < 64; i += 256) {
            int slot = i >> 4, jj = (i >> 3) & 1, c = i & 7;
            *(uint4*)(sm + slot * A_SLOT + (jj ? 129 : 0) * 144 + c * 16) = z;
        }
        if (r2 == 0 || r2 == 63) {      // off-image halo row slot
            char* base = sm + (r2 ? 3 : 0) * A_SLOT;
            for (int i = tid; i < 1170; i += 256)
                *(uint4*)(base + i * 16) = z;
        }
    }

    // ---- async copies: 4 halo rows ----
    #pragma unroll
    for (int sl = 0; sl < 4; sl++) {
        int rimg = 2 * r2 - 1 + sl;
        if ((unsigned)rimg >= (unsigned)HH) continue;
        const char* src = (const char*)XQ + (size_t)(b * 128 + rimg) * 16384;
        uint32_t dstb = alu + (uint32_t)sl * A_SLOT;
        for (int i = tid; i < 1024; i += 256) {
            int px = i >> 3, c = i & 7;
            cp16(dstb + (uint32_t)(px + 1) * 144u + (uint32_t)c * 16u,
                 src + px * 128 + c * 16);
        }
    }
    asm volatile("cp.async.commit_group;" ::: "memory");
    asm volatile("cp.async.wait_group 0;" ::: "memory");
    __syncthreads();

    float cacc[2][NT][4];
    #pragma unroll
    for (int mt = 0; mt < 2; mt++)
        #pragma unroll
        for (int nt = 0; nt < NT; nt++)
            #pragma unroll
            for (int j = 0; j < 4; j++) cacc[mt][nt][j] = 0.f;

    // ---- mainloop: 9 taps x 4 kc, fully unrolled ----
    #pragma unroll
    for (int dy = 0; dy < 3; dy++)
    #pragma unroll
    for (int dx = 0; dx < 3; dx++) {
        const int tap = dy * 3 + dx;
        const uint32_t aB = alu + (uint32_t)(lr + dy) * A_SLOT +
                            (uint32_t)(wb + dx) * 144u;
        #pragma unroll
        for (int kc = 0; kc < 4; kc++) {
            const uint32_t kb = (uint32_t)kc * 32u;
            uint32_t ah[2][4];
            ldsm4(ah[0], aB + kb + aoff);
            ldsm4(ah[1], aB + 16u * 144u + kb + aoff);

            // coalesced B: block q at +q*128 uints, lane*4 within block
            const uint32_t* fb = wFl + ((size_t)tap * 4 + kc) * 512 + lane * 4;
            uint32_t bh[2 * NT];
            if (!LAST) {
                uint4 q0 = *(const uint4*)fb;
                uint4 q1 = *(const uint4*)(fb + 128);
                uint4 q2 = *(const uint4*)(fb + 256);
                uint4 q3 = *(const uint4*)(fb + 384);
                bh[0] = q0.x; bh[1] = q0.y; bh[2] = q0.z; bh[3] = q0.w;
                bh[4] = q1.x; bh[5] = q1.y; bh[6] = q1.z; bh[7] = q1.w;
                bh[8] = q2.x; bh[9] = q2.y; bh[10] = q2.z; bh[11] = q2.w;
                bh[12] = q3.x; bh[13] = q3.y; bh[14] = q3.z; bh[15] = q3.w;
            } else {
                uint4 q0 = *(const uint4*)fb;
                uint4 q1 = *(const uint4*)(fb + 128);
                uint2 q2 = *(const uint2*)(fb + 256);
                bh[0] = q0.x; bh[1] = q0.y; bh[2] = q0.z; bh[3] = q0.w;
                bh[4] = q1.x; bh[5] = q1.y; bh[6] = q1.z; bh[7] = q1.w;
                bh[8] = q2.x; bh[9] = q2.y;
            }

            #pragma unroll
            for (int mt = 0; mt < 2; mt++)
                #pragma unroll
                for (int nt = 0; nt < NT; nt++)
                    mma16816(cacc[mt][nt], ah[mt], &bh[2 * nt]);
        }
    }
    __syncthreads();   // A region now reusable as acc

    // ---- accumulators -> smem [256 px][66-stride fp32] ----
    float* acc = (float*)sm;
    {
        const int rbase = wid * 32 + (lane >> 2);
        const int cb = (lane & 3) * 2;
        #pragma unroll
        for (int mt = 0; mt < 2; mt++)
            #pragma unroll
            for (int nt = 0; nt < NT; nt++) {
                int row = rbase + mt * 16, col = cb + nt * 8;
                *(float2*)&acc[row * 66 + col] =
                    make_float2(cacc[mt][nt][0], cacc[mt][nt][1]);
                *(float2*)&acc[(row + 8) * 66 + col] =
                    make_float2(cacc[mt][nt][2], cacc[mt][nt][3]);
            }
    }
    __syncthreads();

    if (!LAST) {
        // ---- epilogue: one thread per pixel, tanh -> fp16 plane ----
        const int px = tid;
        const int rowg = 2 * r2 + (px >> 7), w = px & 127;
        const float* shp = (const float*)(sm + SH_OFF);
        const float* ap = acc + px * 66;
        unsigned hp[32];
        #pragma unroll
        for (int j = 0; j < 32; j++) {
            float2 vv = *(const float2*)&ap[2 * j];
            float t0 = tanh_fast(vv.x + shp[2 * j]);
            float t1 = tanh_fast(vv.y + shp[2 * j + 1]);
            hp[j] = (unsigned)__half_as_ushort(__float2half_rn(t0)) |
                    ((unsigned)__half_as_ushort(__float2half_rn(t1)) << 16);
        }
        uint4* dh = (uint4*)(YQ + ((size_t)(b * 128 + rowg) * 128 + w) * 64);
        #pragma unroll
        for (int q = 0; q < 8; q++)
            dh[q] = make_uint4(hp[4*q], hp[4*q+1], hp[4*q+2], hp[4*q+3]);
    } else {
        // ---- epilogue: one thread per pixel, tanh(36) + bcoef einsum ----
        const int px = tid;
        const int rowg = 2 * r2 + (px >> 7), w = px & 127;
        const int pixg = rowg * 128 + w;
        const float* shp = (const float*)(sm + SH_OFF);
        const float* basS = (const float*)(sm + BAS_OFF);
        const float* ap = acc + px * 66;
        float hm[36];
        #pragma unroll
        for (int oc = 0; oc < 36; oc++)
            hm[oc] = tanh_fast(ap[oc] + shp[oc]);
        #pragma unroll
        for (int m = 0; m < 6; m++)
            #pragma unroll
            for (int l = 0; l < 9; l++) {
                float s = 0.f;
                #pragma unroll
                for (int k = 0; k < 6; k++)
                    s = fmaf(hm[m * 6 + k], basS[k * 9 + l], s);
                bco[((size_t)(b * 6 + m) * 9 + l) * HW + pixg] = s;
            }
    }
}

// ---------------------------------------------------------------------------
__global__ __launch_bounds__(256) void dynconv(
    const float* __restrict__ x, const float* __restrict__ bco,
    float* __restrict__ out)
{
    const int b = blockIdx.y;
    const int pix = blockIdx.x * 256 + threadIdx.x;
    const int h = pix >> 7, w = pix & 127;

    float bc[54];
    const float* bcb = bco + (size_t)b * 54 * HW + pix;
    #pragma unroll
    for (int i = 0; i < 54; i++) bc[i] = __ldcs(bcb + (size_t)i * HW);

    bool ok[9]; int off[9];
    #pragma unroll
    for (int dy = 0; dy < 3; dy++)
        #pragma unroll
        for (int dx = 0; dx < 3; dx++) {
            int k = dy * 3 + dx;
            int hh = h + dy - 1, ww = w + dx - 1;
            ok[k] = ((unsigned)hh < HH) && ((unsigned)ww < WWID);
            off[k] = hh * WWID + ww;
        }

    const float* xb = x + (size_t)b * CIN * HW;
    float* ob = out + (size_t)b * (CIN * 6) * HW + pix;

    for (int c = 0; c < CIN; c++) {
        const float* xc = xb + c * HW;
        float v[9];
        #pragma unroll
        for (int k = 0; k < 9; k++) v[k] = ok[k] ? __ldg(xc + off[k]) : 0.f;
        #pragma unroll
        for (int m = 0; m < 6; m++) {
            float s = 0.f;
            #pragma unroll
            for (int k = 0; k < 9; k++) s = fmaf(bc[m * 9 + k], v[k], s);
            __stcs(ob + (size_t)(c * 6 + m) * HW, s);
        }
    }
}

// ---------------------------------------------------------------------------
extern "C" void kernel_launch(void* const* d_in, const int* in_sizes, int n_in,
                              void* d_out, int out_size) {
    const float* x    = (const float*)d_in[0];
    const float* w0   = (const float*)d_in[1];
    const float* b0   = (const float*)d_in[2];
    const float* g0   = (const float*)d_in[3];
    const float* be0  = (const float*)d_in[4];
    const float* m0   = (const float*)d_in[5];
    const float* v0   = (const float*)d_in[6];
    const float* wm   = (const float*)d_in[7];
    const float* bm   = (const float*)d_in[8];
    const float* gm   = (const float*)d_in[9];
    const float* bem  = (const float*)d_in[10];
    const float* mm   = (const float*)d_in[11];
    const float* vm   = (const float*)d_in[12];
    const float* wl   = (const float*)d_in[13];
    const float* bl   = (const float*)d_in[14];
    const float* gl   = (const float*)d_in[15];
    const float* bel  = (const float*)d_in[16];
    const float* ml   = (const float*)d_in[17];
    const float* vl   = (const float*)d_in[18];
    const float* bases= (const float*)d_in[19];

    __half *q0, *q1;
    float *bco, *shiftT;
    uint32_t* wF;
    cudaGetSymbolAddress((void**)&q0, g_q0);
    cudaGetSymbolAddress((void**)&q1, g_q1);
    cudaGetSymbolAddress((void**)&bco,  g_bcoef);
    cudaGetSymbolAddress((void**)&wF,   g_wF);
    cudaGetSymbolAddress((void**)&shiftT, g_shiftT);

    cudaFuncSetAttribute(conv_mma_t<0>, cudaFuncAttributeMaxDynamicSharedMemorySize, SMEM_BYTES);
    cudaFuncSetAttribute(conv_mma_t<1>, cudaFuncAttributeMaxDynamicSharedMemorySize, SMEM_BYTES);

    dim3 pgrd(9, 7);
    prep_weights<<<pgrd, 256>>>(w0, b0, g0, be0, m0, v0,
                                wm, bm, gm, bem, mm, vm,
                                wl, bl, gl, bel, ml, vl, wF, shiftT);

    dim3 sgrd(128, NBATCH);
    conv_input<<<sgrd, 128>>>(x, q0);

    dim3 cgrd(64, NBATCH);   // 64 row-pairs per batch
    __half* buf[2] = { q0, q1 };
    for (int l = 0; l < 6; l++) {
        conv_mma_t<0><<<cgrd, 256, SMEM_BYTES>>>(
            buf[l & 1], buf[(l + 1) & 1],
            wF + (size_t)l * 9 * 2048, shiftT + l * 64, nullptr, nullptr);
    }
    // last layer (64->36, n40 tiles) + bcoef, reads layer-5 output plane (q0)
    conv_mma_t<1><<<cgrd, 256, SMEM_BYTES>>>(
        q0, nullptr,
        wF + (size_t)6 * 9 * 2048, shiftT + 6 * 64, bases, bco);

    dim3 grd2(HW / 256, NBATCH);
    dynconv<<<grd2, 256>>>(x, bco, (float*)d_out);
}